// round 1
// baseline (speedup 1.0000x reference)
#include <cuda_runtime.h>
#include <cstdint>

#define BATCH 8
#define NCAND 2535   // 3*13*13 + 3*26*26
#define TOPK 300

// ---------------- scratch (device globals; no allocation) ----------------
__device__ float g_act1[BATCH * 32  * 208 * 208];
__device__ float g_act2[BATCH * 64  * 104 * 104];
__device__ float g_act3[BATCH * 128 * 52  * 52];
__device__ float g_act4[BATCH * 256 * 26  * 26];
__device__ float g_act5[BATCH * 512 * 13  * 13];
__device__ float g_feat1[BATCH * 255 * 13 * 13];
__device__ float g_feat2[BATCH * 255 * 26 * 26];
__device__ float g_cand[BATCH * NCAND * 8]; // ymin,xmin,ymax,xmax,obj,cc,label,score

// ---------------- generic conv: KSxKS, stride S, optional leaky relu ------
// tile: 32 couts x 32 pixels, 256 threads, 4 couts per thread.
// SAME padding for these shapes: pad lo = 0, pad hi = 1 (k=3,s=2) / none (k=1,s=1).
template <int KS, int STRIDE, bool LRELU>
__global__ void conv_kernel(const float* __restrict__ in,
                            const float* __restrict__ w,
                            const float* __restrict__ bias,
                            float* __restrict__ out,
                            int Cin, int Cout,
                            int Hin, int Win, int Hout, int Wout)
{
    constexpr int KK = KS * KS;
    const int b  = blockIdx.z;
    const int ct = blockIdx.y;
    const int pt = blockIdx.x;
    const int tid = threadIdx.x;
    const int tx = tid & 31;   // pixel lane
    const int ty = tid >> 5;   // 0..7 cout group
    const int P  = Hout * Wout;
    const int p  = pt * 32 + tx;
    const bool pvalid = p < P;
    const int oy = pvalid ? (p / Wout) : 0;
    const int ox = pvalid ? (p % Wout) : 0;
    const int iy0 = oy * STRIDE;
    const int ix0 = ox * STRIDE;

    __shared__ float ws[8][32][KK];

    float acc[4] = {0.f, 0.f, 0.f, 0.f};
    const float* inb = in + (size_t)b * Cin * Hin * Win;

    for (int c0 = 0; c0 < Cin; c0 += 8) {
        const int ck = (Cin - c0 < 8) ? (Cin - c0) : 8;
        const int total = ck * 32 * KK;
        for (int idx = tid; idx < total; idx += 256) {
            int c   = idx / (32 * KK);
            int rem = idx - c * (32 * KK);
            int co  = rem / KK;
            int k   = rem - co * KK;
            int gco = ct * 32 + co;
            ws[c][co][k] = (gco < Cout)
                ? w[((size_t)gco * Cin + (c0 + c)) * KK + k] : 0.f;
        }
        __syncthreads();
        if (pvalid) {
            for (int c = 0; c < ck; c++) {
                const float* ic = inb + (size_t)(c0 + c) * Hin * Win;
                #pragma unroll
                for (int ky = 0; ky < KS; ky++) {
                    int iy = iy0 + ky;
                    #pragma unroll
                    for (int kx = 0; kx < KS; kx++) {
                        int ix = ix0 + kx;
                        float v = (iy < Hin && ix < Win) ? ic[iy * Win + ix] : 0.f;
                        int k = ky * KS + kx;
                        #pragma unroll
                        for (int r = 0; r < 4; r++)
                            acc[r] += ws[c][ty * 4 + r][k] * v;
                    }
                }
            }
        }
        __syncthreads();
    }

    if (pvalid) {
        #pragma unroll
        for (int r = 0; r < 4; r++) {
            int gco = ct * 32 + ty * 4 + r;
            if (gco < Cout) {
                float v = acc[r] + bias[gco];
                if (LRELU) v = (v > 0.f) ? v : 0.1f * v;
                out[((size_t)b * Cout + gco) * P + p] = v;
            }
        }
    }
}

// ---------------- decode: feat -> candidate record ----------------
__device__ __forceinline__ float sigmoidf_(float x) { return 1.f / (1.f + expf(-x)); }

__global__ void decode_kernel(const float* __restrict__ feat1,
                              const float* __restrict__ feat2,
                              float* __restrict__ cand)
{
    int idx = blockIdx.x * blockDim.x + threadIdx.x;
    if (idx >= BATCH * NCAND) return;
    int b = idx / NCAND;
    int n = idx - b * NCAND;

    const float A1w[3] = {81.f, 135.f, 344.f}, A1h[3] = {82.f, 169.f, 319.f};
    const float A2w[3] = {10.f, 23.f,  37.f},  A2h[3] = {14.f, 27.f,  58.f};

    const float* fb;
    int H, W, a, yy, xx;
    float aw, ah;
    if (n < 507) {
        H = 13; W = 13;
        a = n / 169; int r = n - a * 169; yy = r / 13; xx = r - yy * 13;
        aw = A1w[a]; ah = A1h[a];
        fb = feat1 + (size_t)b * 255 * 169;
    } else {
        int m = n - 507;
        H = 26; W = 26;
        a = m / 676; int r = m - a * 676; yy = r / 26; xx = r - yy * 26;
        aw = A2w[a]; ah = A2h[a];
        fb = feat2 + (size_t)b * 255 * 676;
    }
    const int HW = H * W;
    const float* base = fb + (size_t)(a * 85) * HW + yy * W + xx;

    float t0 = base[0];
    float t1 = base[HW];
    float t2 = base[2 * HW];
    float t3 = base[3 * HW];
    float t4 = base[4 * HW];

    float bx = (sigmoidf_(t0) + (float)xx) / (float)W;
    float by = (sigmoidf_(t1) + (float)yy) / (float)H;
    float bw = expf(t2) * aw / 416.f;
    float bh = expf(t3) * ah / 416.f;
    float obj = sigmoidf_(t4);

    float ml = base[5 * HW];
    int lab = 0;
    for (int c = 1; c < 80; c++) {
        float v = base[(5 + c) * HW];
        if (v > ml) { ml = v; lab = c; }
    }
    float cc = sigmoidf_(ml);
    float score = obj * cc;
    if (!(score >= 0.1f)) score = 0.f;

    float* o = cand + (size_t)idx * 8;
    o[0] = (by - bh * 0.5f) * 416.f;
    o[1] = (bx - bw * 0.5f) * 416.f;
    o[2] = (by + bh * 0.5f) * 416.f;
    o[3] = (bx + bw * 0.5f) * 416.f;
    o[4] = obj;
    o[5] = cc;
    o[6] = (float)lab;
    o[7] = score;
}

// ---------------- per-image top-k + greedy NMS ----------------
__device__ __forceinline__ void argmax2(float& v, int& i, float v2, int i2)
{
    if (v2 > v || (v2 == v && i2 < i)) { v = v2; i = i2; }
}

__global__ void nms_kernel(const float* __restrict__ cand, float* __restrict__ out)
{
    const int b = blockIdx.x;
    const int tid = threadIdx.x; // 512 threads
    const int lane = tid & 31;
    const int wid  = tid >> 5;   // 16 warps

    __shared__ float s[NCAND];
    __shared__ int   sel[TOPK];
    __shared__ float wv[16];
    __shared__ int   wi[16];

    const float* cb = cand + (size_t)b * NCAND * 8;
    for (int i = tid; i < NCAND; i += 512) s[i] = cb[i * 8 + 7];
    __syncthreads();

    // top-300: 300 rounds of block argmax (value desc, index asc tiebreak)
    for (int r = 0; r < TOPK; r++) {
        float bv = -1.f; int bi = NCAND + 1;
        for (int i = tid; i < NCAND; i += 512)
            argmax2(bv, bi, s[i], i);
        #pragma unroll
        for (int o = 16; o > 0; o >>= 1) {
            float v2 = __shfl_down_sync(0xffffffffu, bv, o);
            int   i2 = __shfl_down_sync(0xffffffffu, bi, o);
            argmax2(bv, bi, v2, i2);
        }
        if (lane == 0) { wv[wid] = bv; wi[wid] = bi; }
        __syncthreads();
        if (wid == 0) {
            float v = (lane < 16) ? wv[lane] : -3.f;
            int   i = (lane < 16) ? wi[lane] : NCAND + 2;
            #pragma unroll
            for (int o = 8; o > 0; o >>= 1) {
                float v2 = __shfl_down_sync(0xffffffffu, v, o);
                int   i2 = __shfl_down_sync(0xffffffffu, i, o);
                argmax2(v, i, v2, i2);
            }
            if (lane == 0) { sel[r] = i; s[i] = -2.f; }
        }
        __syncthreads();
    }

    // load selected boxes
    __shared__ float y0s[TOPK], x0s[TOPK], y1s[TOPK], x1s[TOPK], areas[TOPK];
    __shared__ int labs[TOPK];
    __shared__ unsigned char keep[TOPK];
    if (tid < TOPK) {
        int ii = sel[tid];
        float y0 = cb[ii * 8 + 0], x0 = cb[ii * 8 + 1];
        float y1 = cb[ii * 8 + 2], x1 = cb[ii * 8 + 3];
        y0s[tid] = y0; x0s[tid] = x0; y1s[tid] = y1; x1s[tid] = x1;
        areas[tid] = (y1 - y0) * (x1 - x0);
        labs[tid] = (int)cb[ii * 8 + 6];
        keep[tid] = (cb[ii * 8 + 7] > 0.f) ? 1 : 0;
    }
    __syncthreads();

    // sequential greedy suppression (matches the fori_loop semantics)
    for (int j = 0; j < TOPK - 1; j++) {
        if (tid > j && tid < TOPK && keep[j] && keep[tid] && labs[tid] == labs[j]) {
            float ty0 = fmaxf(y0s[tid], y0s[j]);
            float tx0 = fmaxf(x0s[tid], x0s[j]);
            float ty1 = fminf(y1s[tid], y1s[j]);
            float tx1 = fminf(x1s[tid], x1s[j]);
            float ih = fmaxf(ty1 - ty0, 0.f);
            float iw = fmaxf(tx1 - tx0, 0.f);
            float inter = ih * iw;
            float iou = inter / (areas[tid] + areas[j] - inter + 1e-9f);
            if (iou > 0.5f) keep[tid] = 0;
        }
        __syncthreads();
    }

    if (tid < TOPK) {
        float* o = out + ((size_t)b * TOPK + tid) * 7;
        if (keep[tid]) {
            int ii = sel[tid];
            o[0] = y0s[tid]; o[1] = x0s[tid]; o[2] = y1s[tid]; o[3] = x1s[tid];
            o[4] = cb[ii * 8 + 4];
            o[5] = cb[ii * 8 + 5];
            o[6] = (float)labs[tid];
        } else {
            #pragma unroll
            for (int k = 0; k < 7; k++) o[k] = 0.f;
        }
    }
}

// ---------------- launch ----------------
static inline int ceil_div(int a, int b) { return (a + b - 1) / b; }

extern "C" void kernel_launch(void* const* d_in, const int* in_sizes, int n_in,
                              void* d_out, int out_size)
{
    (void)in_sizes; (void)n_in; (void)out_size;
    const float* images = (const float*)d_in[0];
    const float* w1 = (const float*)d_in[1];  const float* b1 = (const float*)d_in[2];
    const float* w2 = (const float*)d_in[3];  const float* b2 = (const float*)d_in[4];
    const float* w3 = (const float*)d_in[5];  const float* b3 = (const float*)d_in[6];
    const float* w4 = (const float*)d_in[7];  const float* b4 = (const float*)d_in[8];
    const float* w5 = (const float*)d_in[9];  const float* b5 = (const float*)d_in[10];
    const float* wh1 = (const float*)d_in[11]; const float* bh1 = (const float*)d_in[12];
    const float* wh2 = (const float*)d_in[13]; const float* bh2 = (const float*)d_in[14];
    float* out = (float*)d_out;

    static float *act1 = nullptr, *act2, *act3, *act4, *act5, *feat1, *feat2, *cand;
    if (!act1) {
        cudaGetSymbolAddress((void**)&act1, g_act1);
        cudaGetSymbolAddress((void**)&act2, g_act2);
        cudaGetSymbolAddress((void**)&act3, g_act3);
        cudaGetSymbolAddress((void**)&act4, g_act4);
        cudaGetSymbolAddress((void**)&act5, g_act5);
        cudaGetSymbolAddress((void**)&feat1, g_feat1);
        cudaGetSymbolAddress((void**)&feat2, g_feat2);
        cudaGetSymbolAddress((void**)&cand, g_cand);
    }

    // L1: 3 -> 32, 416 -> 208
    {
        dim3 grid(ceil_div(208 * 208, 32), 1, BATCH);
        conv_kernel<3, 2, true><<<grid, 256>>>(images, w1, b1, act1, 3, 32, 416, 416, 208, 208);
    }
    // L2: 32 -> 64, 208 -> 104
    {
        dim3 grid(ceil_div(104 * 104, 32), 2, BATCH);
        conv_kernel<3, 2, true><<<grid, 256>>>(act1, w2, b2, act2, 32, 64, 208, 208, 104, 104);
    }
    // L3: 64 -> 128, 104 -> 52
    {
        dim3 grid(ceil_div(52 * 52, 32), 4, BATCH);
        conv_kernel<3, 2, true><<<grid, 256>>>(act2, w3, b3, act3, 64, 128, 104, 104, 52, 52);
    }
    // L4: 128 -> 256, 52 -> 26
    {
        dim3 grid(ceil_div(26 * 26, 32), 8, BATCH);
        conv_kernel<3, 2, true><<<grid, 256>>>(act3, w4, b4, act4, 128, 256, 52, 52, 26, 26);
    }
    // head2: 256 -> 255 @ 26x26
    {
        dim3 grid(ceil_div(26 * 26, 32), ceil_div(255, 32), BATCH);
        conv_kernel<1, 1, false><<<grid, 256>>>(act4, wh2, bh2, feat2, 256, 255, 26, 26, 26, 26);
    }
    // L5: 256 -> 512, 26 -> 13
    {
        dim3 grid(ceil_div(13 * 13, 32), 16, BATCH);
        conv_kernel<3, 2, true><<<grid, 256>>>(act4, w5, b5, act5, 256, 512, 26, 26, 13, 13);
    }
    // head1: 512 -> 255 @ 13x13
    {
        dim3 grid(ceil_div(13 * 13, 32), ceil_div(255, 32), BATCH);
        conv_kernel<1, 1, false><<<grid, 256>>>(act5, wh1, bh1, feat1, 512, 255, 13, 13, 13, 13);
    }
    // decode
    {
        int total = BATCH * NCAND;
        decode_kernel<<<ceil_div(total, 256), 256>>>(feat1, feat2, cand);
    }
    // nms + output
    nms_kernel<<<BATCH, 512>>>(cand, out);
}

// round 3
// speedup vs baseline: 1.3596x; 1.3596x over previous
#include <cuda_runtime.h>
#include <cstdint>

#define BATCH 8
#define NCAND 2535   // 3*13*13 + 3*26*26
#define TOPK 300

// ---------------- scratch (device globals; no allocation) ----------------
__device__ float g_act1[BATCH * 32  * 208 * 208];
__device__ float g_act2[BATCH * 64  * 104 * 104];
__device__ float g_act3[BATCH * 128 * 52  * 52];
__device__ float g_act4[BATCH * 256 * 26  * 26];
__device__ float g_act5[BATCH * 512 * 13  * 13];
__device__ float g_feat1[BATCH * 255 * 13 * 13];
__device__ float g_feat2[BATCH * 255 * 26 * 26];
__device__ float g_cand[BATCH * NCAND * 8]; // ymin,xmin,ymax,xmax,obj,cc,label,score

// ---------------- conv v2: compile-time dims, 4 couts x 2 vertical pixels ----
// block = 256 threads = 32 pixel-lanes (16 cols x 2 row-pairs) x 8 cout-groups.
// Each thread: 4 couts x 2 vertically-adjacent output pixels (8 accumulators).
// Weights staged in smem padded to 12 floats per filter -> float4 reads.
// SAME padding for these shapes: pad lo = 0, pad hi = 1 (k=3,s=2) / none (1x1).
template <int KS, int STRIDE, bool LRELU,
          int CIN, int HIN, int WIN, int HOUT, int WOUT, int COUT>
__global__ void __launch_bounds__(256, 3)
conv2_kernel(const float* __restrict__ in,
             const float* __restrict__ w,
             const float* __restrict__ bias,
             float* __restrict__ out)
{
    constexpr int KK   = KS * KS;
    constexpr int WPAD = (KS == 3) ? 12 : 1;   // padded filter row for float4 align
    constexpr int CK   = (CIN < 8) ? CIN : 8;  // channel chunk in smem
    constexpr int ROWS = STRIDE + KS;          // rows needed for 2 vertical pixels
    constexpr int ZC   = (COUT + 31) / 32;
    constexpr int HW_IN = HIN * WIN;
    constexpr int P_OUT = HOUT * WOUT;

    const int tid  = threadIdx.x;
    const int lane = tid & 31;
    const int ty   = tid >> 5;          // 0..7 cout group
    const int lx   = lane & 15;         // output col within tile
    const int lyy  = lane >> 4;         // 0/1 row-pair

    const int b   = blockIdx.z / ZC;
    const int czi = blockIdx.z - b * ZC;
    const int co_base = czi * 32;

    const int ox  = blockIdx.x * 16 + lx;
    const int oy0 = blockIdx.y * 4 + lyy * 2;

    const int ix0 = ox * STRIDE;
    const int iy_base = oy0 * STRIDE;
    const int idx0 = iy_base * WIN + ix0;

    // hoisted bounds predicates
    bool pr[ROWS], pc[KS];
    #pragma unroll
    for (int r = 0; r < ROWS; r++) pr[r] = (iy_base + r) < HIN;
    #pragma unroll
    for (int k = 0; k < KS; k++)  pc[k] = (ix0 + k) < WIN;

    __shared__ __align__(16) float ws[CK][32][WPAD];

    float acc[2][4];
    #pragma unroll
    for (int p = 0; p < 2; p++)
        #pragma unroll
        for (int r = 0; r < 4; r++) acc[p][r] = 0.f;

    const float* inb = in + (size_t)b * CIN * HW_IN;

    for (int c0 = 0; c0 < CIN; c0 += CK) {
        // cooperative weight stage
        constexpr int TOTAL = CK * 32 * WPAD;
        for (int idx = tid; idx < TOTAL; idx += 256) {
            int k  = idx % WPAD;
            int co = (idx / WPAD) & 31;
            int c  = idx / (WPAD * 32);
            int gco = co_base + co;
            float v = 0.f;
            if (k < KK && gco < COUT)
                v = w[((size_t)gco * CIN + (c0 + c)) * KK + k];
            ws[c][co][k] = v;
        }
        __syncthreads();

        #pragma unroll 4
        for (int c = 0; c < CK; c++) {
            const float* ic = inb + (size_t)(c0 + c) * HW_IN + idx0;

            // input taps
            float iv[ROWS][KS];
            #pragma unroll
            for (int r = 0; r < ROWS; r++)
                #pragma unroll
                for (int k = 0; k < KS; k++)
                    iv[r][k] = (pr[r] && pc[k]) ? __ldg(ic + r * WIN + k) : 0.f;

            // weights for my 4 couts (vectorized smem reads)
            float wr[4][KK];
            #pragma unroll
            for (int r = 0; r < 4; r++) {
                const float* wbse = &ws[c][ty * 4 + r][0];
                if (KS == 3) {
                    float4 a = *reinterpret_cast<const float4*>(wbse);
                    float4 d = *reinterpret_cast<const float4*>(wbse + 4);
                    wr[r][0] = a.x; wr[r][1] = a.y; wr[r][2] = a.z; wr[r][3] = a.w;
                    wr[r][4] = d.x; wr[r][5] = d.y; wr[r][6] = d.z; wr[r][7] = d.w;
                    wr[r][8] = wbse[8];
                } else {
                    wr[r][0] = wbse[0];
                }
            }

            // accumulate: 2 pixels x 4 couts x KK taps
            #pragma unroll
            for (int px = 0; px < 2; px++) {
                #pragma unroll
                for (int ky = 0; ky < KS; ky++) {
                    #pragma unroll
                    for (int kx = 0; kx < KS; kx++) {
                        float v = iv[px * STRIDE + ky][kx];
                        #pragma unroll
                        for (int r = 0; r < 4; r++)
                            acc[px][r] = fmaf(wr[r][ky * KS + kx], v, acc[px][r]);
                    }
                }
            }
        }
        __syncthreads();
    }

    // store
    if (ox < WOUT) {
        #pragma unroll
        for (int px = 0; px < 2; px++) {
            int oy = oy0 + px;
            if (oy < HOUT) {
                #pragma unroll
                for (int r = 0; r < 4; r++) {
                    int gco = co_base + ty * 4 + r;
                    if (gco < COUT) {
                        float v = acc[px][r] + bias[gco];
                        if (LRELU) v = (v > 0.f) ? v : 0.1f * v;
                        out[((size_t)b * COUT + gco) * P_OUT + oy * WOUT + ox] = v;
                    }
                }
            }
        }
    }
}

// ---------------- decode: feat -> candidate record ----------------
__device__ __forceinline__ float sigmoidf_(float x) { return 1.f / (1.f + expf(-x)); }

__global__ void decode_kernel(const float* __restrict__ feat1,
                              const float* __restrict__ feat2,
                              float* __restrict__ cand)
{
    int idx = blockIdx.x * blockDim.x + threadIdx.x;
    if (idx >= BATCH * NCAND) return;
    int b = idx / NCAND;
    int n = idx - b * NCAND;

    const float A1w[3] = {81.f, 135.f, 344.f}, A1h[3] = {82.f, 169.f, 319.f};
    const float A2w[3] = {10.f, 23.f,  37.f},  A2h[3] = {14.f, 27.f,  58.f};

    const float* fb;
    int H, W, a, yy, xx;
    float aw, ah;
    if (n < 507) {
        H = 13; W = 13;
        a = n / 169; int r = n - a * 169; yy = r / 13; xx = r - yy * 13;
        aw = A1w[a]; ah = A1h[a];
        fb = feat1 + (size_t)b * 255 * 169;
    } else {
        int m = n - 507;
        H = 26; W = 26;
        a = m / 676; int r = m - a * 676; yy = r / 26; xx = r - yy * 26;
        aw = A2w[a]; ah = A2h[a];
        fb = feat2 + (size_t)b * 255 * 676;
    }
    const int HW = H * W;
    const float* base = fb + (size_t)(a * 85) * HW + yy * W + xx;

    float t0 = base[0];
    float t1 = base[HW];
    float t2 = base[2 * HW];
    float t3 = base[3 * HW];
    float t4 = base[4 * HW];

    float bx = (sigmoidf_(t0) + (float)xx) / (float)W;
    float by = (sigmoidf_(t1) + (float)yy) / (float)H;
    float bw = expf(t2) * aw / 416.f;
    float bh = expf(t3) * ah / 416.f;
    float obj = sigmoidf_(t4);

    float ml = base[5 * HW];
    int lab = 0;
    for (int c = 1; c < 80; c++) {
        float v = base[(5 + c) * HW];
        if (v > ml) { ml = v; lab = c; }
    }
    float cc = sigmoidf_(ml);
    float score = obj * cc;
    if (!(score >= 0.1f)) score = 0.f;

    float* o = cand + (size_t)idx * 8;
    o[0] = (by - bh * 0.5f) * 416.f;
    o[1] = (bx - bw * 0.5f) * 416.f;
    o[2] = (by + bh * 0.5f) * 416.f;
    o[3] = (bx + bw * 0.5f) * 416.f;
    o[4] = obj;
    o[5] = cc;
    o[6] = (float)lab;
    o[7] = score;
}

// ---------------- per-image top-k + greedy NMS ----------------
__device__ __forceinline__ void argmax2(float& v, int& i, float v2, int i2)
{
    if (v2 > v || (v2 == v && i2 < i)) { v = v2; i = i2; }
}

__global__ void nms_kernel(const float* __restrict__ cand, float* __restrict__ out)
{
    const int b = blockIdx.x;
    const int tid = threadIdx.x; // 512 threads
    const int lane = tid & 31;
    const int wid  = tid >> 5;   // 16 warps

    __shared__ float s[NCAND];
    __shared__ int   sel[TOPK];
    __shared__ float wv[16];
    __shared__ int   wi[16];

    const float* cb = cand + (size_t)b * NCAND * 8;
    for (int i = tid; i < NCAND; i += 512) s[i] = cb[i * 8 + 7];
    __syncthreads();

    // top-300: 300 rounds of block argmax (value desc, index asc tiebreak)
    for (int r = 0; r < TOPK; r++) {
        float bv = -1.f; int bi = NCAND + 1;
        for (int i = tid; i < NCAND; i += 512)
            argmax2(bv, bi, s[i], i);
        #pragma unroll
        for (int o = 16; o > 0; o >>= 1) {
            float v2 = __shfl_down_sync(0xffffffffu, bv, o);
            int   i2 = __shfl_down_sync(0xffffffffu, bi, o);
            argmax2(bv, bi, v2, i2);
        }
        if (lane == 0) { wv[wid] = bv; wi[wid] = bi; }
        __syncthreads();
        if (wid == 0) {
            float v = (lane < 16) ? wv[lane] : -3.f;
            int   i = (lane < 16) ? wi[lane] : NCAND + 2;
            #pragma unroll
            for (int o = 8; o > 0; o >>= 1) {
                float v2 = __shfl_down_sync(0xffffffffu, v, o);
                int   i2 = __shfl_down_sync(0xffffffffu, i, o);
                argmax2(v, i, v2, i2);
            }
            if (lane == 0) { sel[r] = i; s[i] = -2.f; }
        }
        __syncthreads();
    }

    // load selected boxes
    __shared__ float y0s[TOPK], x0s[TOPK], y1s[TOPK], x1s[TOPK], areas[TOPK];
    __shared__ int labs[TOPK];
    __shared__ unsigned char keep[TOPK];
    if (tid < TOPK) {
        int ii = sel[tid];
        float y0 = cb[ii * 8 + 0], x0 = cb[ii * 8 + 1];
        float y1 = cb[ii * 8 + 2], x1 = cb[ii * 8 + 3];
        y0s[tid] = y0; x0s[tid] = x0; y1s[tid] = y1; x1s[tid] = x1;
        areas[tid] = (y1 - y0) * (x1 - x0);
        labs[tid] = (int)cb[ii * 8 + 6];
        keep[tid] = (cb[ii * 8 + 7] > 0.f) ? 1 : 0;
    }
    __syncthreads();

    // sequential greedy suppression (matches the fori_loop semantics)
    for (int j = 0; j < TOPK - 1; j++) {
        if (tid > j && tid < TOPK && keep[j] && keep[tid] && labs[tid] == labs[j]) {
            float ty0 = fmaxf(y0s[tid], y0s[j]);
            float tx0 = fmaxf(x0s[tid], x0s[j]);
            float ty1 = fminf(y1s[tid], y1s[j]);
            float tx1 = fminf(x1s[tid], x1s[j]);
            float ih = fmaxf(ty1 - ty0, 0.f);
            float iw = fmaxf(tx1 - tx0, 0.f);
            float inter = ih * iw;
            float iou = inter / (areas[tid] + areas[j] - inter + 1e-9f);
            if (iou > 0.5f) keep[tid] = 0;
        }
        __syncthreads();
    }

    if (tid < TOPK) {
        float* o = out + ((size_t)b * TOPK + tid) * 7;
        if (keep[tid]) {
            int ii = sel[tid];
            o[0] = y0s[tid]; o[1] = x0s[tid]; o[2] = y1s[tid]; o[3] = x1s[tid];
            o[4] = cb[ii * 8 + 4];
            o[5] = cb[ii * 8 + 5];
            o[6] = (float)labs[tid];
        } else {
            #pragma unroll
            for (int k = 0; k < 7; k++) o[k] = 0.f;
        }
    }
}

// ---------------- launch ----------------
static inline int ceil_div(int a, int b) { return (a + b - 1) / b; }

extern "C" void kernel_launch(void* const* d_in, const int* in_sizes, int n_in,
                              void* d_out, int out_size)
{
    (void)in_sizes; (void)n_in; (void)out_size;
    const float* images = (const float*)d_in[0];
    const float* w1 = (const float*)d_in[1];  const float* b1 = (const float*)d_in[2];
    const float* w2 = (const float*)d_in[3];  const float* b2 = (const float*)d_in[4];
    const float* w3 = (const float*)d_in[5];  const float* b3 = (const float*)d_in[6];
    const float* w4 = (const float*)d_in[7];  const float* b4 = (const float*)d_in[8];
    const float* w5 = (const float*)d_in[9];  const float* b5 = (const float*)d_in[10];
    const float* wh1 = (const float*)d_in[11]; const float* bh1 = (const float*)d_in[12];
    const float* wh2 = (const float*)d_in[13]; const float* bh2 = (const float*)d_in[14];
    float* out = (float*)d_out;

    static float *act1 = nullptr, *act2, *act3, *act4, *act5, *feat1, *feat2, *cand;
    if (!act1) {
        cudaGetSymbolAddress((void**)&act1, g_act1);
        cudaGetSymbolAddress((void**)&act2, g_act2);
        cudaGetSymbolAddress((void**)&act3, g_act3);
        cudaGetSymbolAddress((void**)&act4, g_act4);
        cudaGetSymbolAddress((void**)&act5, g_act5);
        cudaGetSymbolAddress((void**)&feat1, g_feat1);
        cudaGetSymbolAddress((void**)&feat2, g_feat2);
        cudaGetSymbolAddress((void**)&cand, g_cand);
    }

    // L1: 3 -> 32, 416 -> 208
    conv2_kernel<3, 2, true, 3, 416, 416, 208, 208, 32>
        <<<dim3(ceil_div(208,16), ceil_div(208,4), BATCH * 1), 256>>>(images, w1, b1, act1);
    // L2: 32 -> 64, 208 -> 104
    conv2_kernel<3, 2, true, 32, 208, 208, 104, 104, 64>
        <<<dim3(ceil_div(104,16), ceil_div(104,4), BATCH * 2), 256>>>(act1, w2, b2, act2);
    // L3: 64 -> 128, 104 -> 52
    conv2_kernel<3, 2, true, 64, 104, 104, 52, 52, 128>
        <<<dim3(ceil_div(52,16), ceil_div(52,4), BATCH * 4), 256>>>(act2, w3, b3, act3);
    // L4: 128 -> 256, 52 -> 26
    conv2_kernel<3, 2, true, 128, 52, 52, 26, 26, 256>
        <<<dim3(ceil_div(26,16), ceil_div(26,4), BATCH * 8), 256>>>(act3, w4, b4, act4);
    // head2: 256 -> 255 @ 26x26
    conv2_kernel<1, 1, false, 256, 26, 26, 26, 26, 255>
        <<<dim3(ceil_div(26,16), ceil_div(26,4), BATCH * 8), 256>>>(act4, wh2, bh2, feat2);
    // L5: 256 -> 512, 26 -> 13
    conv2_kernel<3, 2, true, 256, 26, 26, 13, 13, 512>
        <<<dim3(ceil_div(13,16), ceil_div(13,4), BATCH * 16), 256>>>(act4, w5, b5, act5);
    // head1: 512 -> 255 @ 13x13
    conv2_kernel<1, 1, false, 512, 13, 13, 13, 13, 255>
        <<<dim3(ceil_div(13,16), ceil_div(13,4), BATCH * 8), 256>>>(act5, wh1, bh1, feat1);
    // decode
    decode_kernel<<<ceil_div(BATCH * NCAND, 256), 256>>>(feat1, feat2, cand);
    // nms + output
    nms_kernel<<<BATCH, 512>>>(cand, out);
}